// round 2
// baseline (speedup 1.0000x reference)
#include <cuda_runtime.h>
#include <cuda_bf16.h>
#include <math.h>

#define NN 50000
#define EE 800000
#define DD 128
#define HH 8

// ---------------- scratch (device globals; no allocation allowed) ----------------
__device__ float g_xl[NN * DD];
__device__ float g_xr[NN * DD];
__device__ float g_num[NN * DD];
__device__ float g_denom[NN * HH];
__device__ float g_h1[NN * DD];

// ---------------- zero accumulators ----------------
__global__ void k_zero() {
    int i = blockIdx.x * 256 + threadIdx.x;
    if (i < NN * DD) g_num[i] = 0.f;
    int i2 = i - NN * DD;
    if (i2 >= 0 && i2 < NN * HH) g_denom[i2] = 0.f;
}

// ---------------- node transforms: xl = x@Wl + bl, xr = x@Wr + br ----------------
__global__ void __launch_bounds__(128) k_node_lin(
    const float* __restrict__ x,
    const float* __restrict__ Wl, const float* __restrict__ bl,
    const float* __restrict__ Wr, const float* __restrict__ br)
{
    __shared__ float xs[32][DD];
    int base = blockIdx.x * 32;
    int tid = threadIdx.x;
    for (int i = tid; i < 32 * DD; i += 128) {
        int n = i >> 7, k = i & 127;
        int gn = base + n;
        xs[n][k] = (gn < NN) ? x[(size_t)gn * DD + k] : 0.f;
    }
    __syncthreads();

    float accl[32], accr[32];
#pragma unroll
    for (int n = 0; n < 32; n++) { accl[n] = 0.f; accr[n] = 0.f; }
    int j = tid;
#pragma unroll 2
    for (int k = 0; k < DD; k += 4) {
        float wl0 = Wl[(k + 0) * DD + j], wl1 = Wl[(k + 1) * DD + j];
        float wl2 = Wl[(k + 2) * DD + j], wl3 = Wl[(k + 3) * DD + j];
        float wr0 = Wr[(k + 0) * DD + j], wr1 = Wr[(k + 1) * DD + j];
        float wr2 = Wr[(k + 2) * DD + j], wr3 = Wr[(k + 3) * DD + j];
#pragma unroll
        for (int n = 0; n < 32; n++) {
            float4 xv = *(const float4*)&xs[n][k];
            accl[n] += xv.x * wl0 + xv.y * wl1 + xv.z * wl2 + xv.w * wl3;
            accr[n] += xv.x * wr0 + xv.y * wr1 + xv.z * wr2 + xv.w * wr3;
        }
    }
    float bjl = bl[j], bjr = br[j];
#pragma unroll
    for (int n = 0; n < 32; n++) {
        int gn = base + n;
        if (gn < NN) {
            g_xl[(size_t)gn * DD + j] = accl[n] + bjl;
            g_xr[(size_t)gn * DD + j] = accr[n] + bjr;
        }
    }
}

// ---------------- edge kernel: ee GEMV + logits + exp + atomic num/denom ----------------
__global__ void __launch_bounds__(128) k_edge(
    const float* __restrict__ ea,
    const int* __restrict__ ei,
    const float* __restrict__ We,
    const float* __restrict__ att)
{
    __shared__ float es[32][DD];
    __shared__ int ssrc[32], sdst[32];
    int tid = threadIdx.x;
    int j = tid;
    float att_j = att[j];
    int ntiles = EE / 32;  // 25000, exact

    for (int t = blockIdx.x; t < ntiles; t += gridDim.x) {
        int ebase = t * 32;
        for (int i = tid; i < 32 * DD; i += 128) {
            int n = i >> 7, k = i & 127;
            es[n][k] = ea[(size_t)(ebase + n) * DD + k];
        }
        if (tid < 32) ssrc[tid] = ei[ebase + tid];
        else if (tid < 64) sdst[tid - 32] = ei[EE + ebase + (tid - 32)];
        __syncthreads();

        float acc[32];
#pragma unroll
        for (int n = 0; n < 32; n++) acc[n] = 0.f;

#pragma unroll 2
        for (int k = 0; k < DD; k += 4) {
            float w0 = We[(k + 0) * DD + j], w1 = We[(k + 1) * DD + j];
            float w2 = We[(k + 2) * DD + j], w3 = We[(k + 3) * DD + j];
#pragma unroll
            for (int n = 0; n < 32; n++) {
                float4 ev = *(const float4*)&es[n][k];
                acc[n] += ev.x * w0 + ev.y * w1 + ev.z * w2 + ev.w * w3;
            }
        }

        // per-edge attention: logits, exp (no max-shift; mathematically identical),
        // atomic accumulation of numerator and denominator
#pragma unroll
        for (int n = 0; n < 32; n++) {
            int s = ssrc[n], d = sdst[n];
            float xls = g_xl[(size_t)s * DD + j];
            float xrd = g_xr[(size_t)d * DD + j];
            float mm = acc[n] + xls + xrd;
            mm = (mm > 0.f) ? mm : 0.2f * mm;   // leaky relu, slope 0.2
            float p = mm * att_j;
            p += __shfl_xor_sync(0xffffffffu, p, 8);
            p += __shfl_xor_sync(0xffffffffu, p, 4);
            p += __shfl_xor_sync(0xffffffffu, p, 2);
            p += __shfl_xor_sync(0xffffffffu, p, 1);
            float ex = __expf(p);               // per-head logit sum, all 16 lanes have it
            if ((tid & 15) == 0) atomicAdd(&g_denom[(size_t)d * HH + (j >> 4)], ex);
            atomicAdd(&g_num[(size_t)d * DD + j], ex * xls);
        }
        __syncthreads();
    }
}

// ---------------- attention finalize + residual + LN1 ----------------
__global__ void __launch_bounds__(128) k_attn_ln1(
    const float* __restrict__ x,
    const float* __restrict__ batt,
    const float* __restrict__ g1, const float* __restrict__ be1)
{
    int n = blockIdx.x, j = threadIdx.x;
    float num = g_num[(size_t)n * DD + j];
    float den = g_denom[n * HH + (j >> 4)];
    float y = x[(size_t)n * DD + j] + num / (den + 1e-16f) + batt[j];

    float s1 = y, s2 = y * y;
#pragma unroll
    for (int o = 16; o; o >>= 1) {
        s1 += __shfl_xor_sync(0xffffffffu, s1, o);
        s2 += __shfl_xor_sync(0xffffffffu, s2, o);
    }
    __shared__ float r1[4], r2[4];
    int w = j >> 5;
    if ((j & 31) == 0) { r1[w] = s1; r2[w] = s2; }
    __syncthreads();
    float t1 = r1[0] + r1[1] + r1[2] + r1[3];
    float t2 = r2[0] + r2[1] + r2[2] + r2[3];
    float mu = t1 * (1.f / 128.f);
    float var = t2 * (1.f / 128.f) - mu * mu;
    float rs = rsqrtf(var + 1e-5f);
    g_h1[(size_t)n * DD + j] = (y - mu) * rs * g1[j] + be1[j];
}

// ---------------- FFN (gelu exact) + residual + LN2 -> out ----------------
__global__ void __launch_bounds__(256) k_ffn(
    const float* __restrict__ W1, const float* __restrict__ b1,
    const float* __restrict__ W2, const float* __restrict__ b2,
    const float* __restrict__ g2, const float* __restrict__ be2,
    float* __restrict__ out)
{
    __shared__ float hs[16][DD];     // 8 KB
    __shared__ float hid[16][512];   // 32 KB
    int base = blockIdx.x * 16, tid = threadIdx.x;
    for (int i = tid; i < 16 * DD; i += 256) {
        int n = i >> 7, k = i & 127;
        int gn = base + n;
        hs[n][k] = (gn < NN) ? g_h1[(size_t)gn * DD + k] : 0.f;
    }
    __syncthreads();

    // phase A: hidden = gelu(h @ W1 + b1); each thread owns 2 hidden cols x 16 nodes
    float a0[16], a1[16];
#pragma unroll
    for (int n = 0; n < 16; n++) { a0[n] = 0.f; a1[n] = 0.f; }
    int c0 = tid, c1 = tid + 256;
#pragma unroll 2
    for (int k = 0; k < DD; k += 4) {
        float u0 = W1[(k + 0) * 512 + c0], u1 = W1[(k + 1) * 512 + c0];
        float u2 = W1[(k + 2) * 512 + c0], u3 = W1[(k + 3) * 512 + c0];
        float v0 = W1[(k + 0) * 512 + c1], v1 = W1[(k + 1) * 512 + c1];
        float v2 = W1[(k + 2) * 512 + c1], v3 = W1[(k + 3) * 512 + c1];
#pragma unroll
        for (int n = 0; n < 16; n++) {
            float4 hv = *(const float4*)&hs[n][k];
            a0[n] += hv.x * u0 + hv.y * u1 + hv.z * u2 + hv.w * u3;
            a1[n] += hv.x * v0 + hv.y * v1 + hv.z * v2 + hv.w * v3;
        }
    }
    float bb0 = b1[c0], bb1 = b1[c1];
#pragma unroll
    for (int n = 0; n < 16; n++) {
        float v = a0[n] + bb0;
        hid[n][c0] = 0.5f * v * (1.f + erff(v * 0.7071067811865475f));
        float u = a1[n] + bb1;
        hid[n][c1] = 0.5f * u * (1.f + erff(u * 0.7071067811865475f));
    }
    __syncthreads();

    // phase B: o = hid @ W2; thread = (out col j, 8-node group)
    float o[8];
#pragma unroll
    for (int m = 0; m < 8; m++) o[m] = 0.f;
    int j = tid & 127, ng = (tid >> 7) * 8;
#pragma unroll 2
    for (int k = 0; k < 512; k += 4) {
        float w0 = W2[(k + 0) * DD + j], w1 = W2[(k + 1) * DD + j];
        float w2 = W2[(k + 2) * DD + j], w3 = W2[(k + 3) * DD + j];
#pragma unroll
        for (int m = 0; m < 8; m++) {
            float4 hv = *(const float4*)&hid[ng + m][k];
            o[m] += hv.x * w0 + hv.y * w1 + hv.z * w2 + hv.w * w3;
        }
    }
    float bj = b2[j];
    // residual back into hs (each (node,col) owned by exactly one thread)
#pragma unroll
    for (int m = 0; m < 8; m++) hs[ng + m][j] = o[m] + bj + hs[ng + m][j];
    __syncthreads();

    // LN2: 8 warps, 2 nodes each
    int w = tid >> 5, lane = tid & 31;
#pragma unroll
    for (int q = 0; q < 2; q++) {
        int nn2 = w * 2 + q;
        float v0 = hs[nn2][lane], v1 = hs[nn2][lane + 32];
        float v2 = hs[nn2][lane + 64], v3 = hs[nn2][lane + 96];
        float s1 = v0 + v1 + v2 + v3;
        float s2 = v0 * v0 + v1 * v1 + v2 * v2 + v3 * v3;
#pragma unroll
        for (int off = 16; off; off >>= 1) {
            s1 += __shfl_xor_sync(0xffffffffu, s1, off);
            s2 += __shfl_xor_sync(0xffffffffu, s2, off);
        }
        float mu = s1 * (1.f / 128.f);
        float var = s2 * (1.f / 128.f) - mu * mu;
        float rs = rsqrtf(var + 1e-5f);
        int gn = base + nn2;
        if (gn < NN) {
            size_t ob = (size_t)gn * DD;
            out[ob + lane]      = (v0 - mu) * rs * g2[lane]      + be2[lane];
            out[ob + lane + 32] = (v1 - mu) * rs * g2[lane + 32] + be2[lane + 32];
            out[ob + lane + 64] = (v2 - mu) * rs * g2[lane + 64] + be2[lane + 64];
            out[ob + lane + 96] = (v3 - mu) * rs * g2[lane + 96] + be2[lane + 96];
        }
    }
}

// ---------------- launch ----------------
extern "C" void kernel_launch(void* const* d_in, const int* in_sizes, int n_in,
                              void* d_out, int out_size)
{
    const float* x    = (const float*)d_in[0];
    const int*   ei   = (const int*)  d_in[1];
    const float* ea   = (const float*)d_in[2];
    // d_in[3] = batch (unused)
    const float* Wl   = (const float*)d_in[4];
    const float* bl   = (const float*)d_in[5];
    const float* Wr   = (const float*)d_in[6];
    const float* br   = (const float*)d_in[7];
    const float* We   = (const float*)d_in[8];
    const float* att  = (const float*)d_in[9];
    const float* batt = (const float*)d_in[10];
    const float* W1   = (const float*)d_in[11];
    const float* b1   = (const float*)d_in[12];
    const float* W2   = (const float*)d_in[13];
    const float* b2   = (const float*)d_in[14];
    const float* g1   = (const float*)d_in[15];
    const float* be1  = (const float*)d_in[16];
    const float* g2   = (const float*)d_in[17];
    const float* be2  = (const float*)d_in[18];
    float* out = (float*)d_out;

    int ztot = NN * DD + NN * HH;
    k_zero<<<(ztot + 255) / 256, 256>>>();
    k_node_lin<<<(NN + 31) / 32, 128>>>(x, Wl, bl, Wr, br);
    k_edge<<<1184, 128>>>(ea, ei, We, att);
    k_attn_ln1<<<NN, 128>>>(x, batt, g1, be1);
    k_ffn<<<(NN + 15) / 16, 256>>>(W1, b1, W2, b2, g2, be2, out);
}

// round 17
// speedup vs baseline: 1.1486x; 1.1486x over previous
#include <cuda_runtime.h>
#include <cuda_bf16.h>
#include <math.h>

#define NN 50000
#define EE 800000
#define DD 128
#define HH 8

typedef unsigned long long ull;

// ---------------- scratch (device globals; no allocation allowed) ----------------
__device__ float g_xl[NN * DD];
__device__ float g_xr[NN * DD];
__device__ float g_num[NN * DD];
__device__ float g_denom[NN * HH];
__device__ float g_h1[NN * DD];

// packed weights: (W[2k][j], W[2k+1][j]) pairs along the reduction dim
__device__ float2 g_Wlp[64 * 128];
__device__ float2 g_Wrp[64 * 128];
__device__ float2 g_Wep[64 * 128];
__device__ float2 g_W1p[64 * 512];
__device__ float2 g_W2p[256 * 128];

// ---------------- f32x2 helpers ----------------
__device__ __forceinline__ void fma2(ull& d, ull a, ull b) {
    asm("fma.rn.f32x2 %0, %1, %2, %0;" : "+l"(d) : "l"(a), "l"(b));
}
__device__ __forceinline__ float sum2(ull v) {
    float lo = __uint_as_float((unsigned)(v & 0xffffffffu));
    float hi = __uint_as_float((unsigned)(v >> 32));
    return lo + hi;
}

// ---------------- init: zero accumulators + pack weights (one launch) ----------------
__global__ void k_init(const float* __restrict__ Wl, const float* __restrict__ Wr,
                       const float* __restrict__ We, const float* __restrict__ W1,
                       const float* __restrict__ W2) {
    int i = blockIdx.x * 256 + threadIdx.x;
    // zero num/denom (6.4M + 400K floats)
    if (i < NN * DD) g_num[i] = 0.f;
    int i2 = i - NN * DD;
    if (i2 >= 0 && i2 < NN * HH) g_denom[i2] = 0.f;
    // pack weights into k-paired float2
    if (i < 64 * 128) {
        int k2 = i >> 7, j = i & 127;
        g_Wlp[i] = make_float2(Wl[(2 * k2) * 128 + j], Wl[(2 * k2 + 1) * 128 + j]);
        g_Wrp[i] = make_float2(Wr[(2 * k2) * 128 + j], Wr[(2 * k2 + 1) * 128 + j]);
        g_Wep[i] = make_float2(We[(2 * k2) * 128 + j], We[(2 * k2 + 1) * 128 + j]);
    }
    if (i < 64 * 512) {
        int k2 = i >> 9, c = i & 511;
        g_W1p[i] = make_float2(W1[(2 * k2) * 512 + c], W1[(2 * k2 + 1) * 512 + c]);
    }
    if (i < 256 * 128) {
        int k2 = i >> 7, j = i & 127;
        g_W2p[i] = make_float2(W2[(2 * k2) * 128 + j], W2[(2 * k2 + 1) * 128 + j]);
    }
}

// ---------------- node transforms: xl = x@Wl + bl, xr = x@Wr + br ----------------
// 256 threads: lower 128 compute xl, upper 128 compute xr (shared x tile)
__global__ void __launch_bounds__(256) k_node_lin(
    const float* __restrict__ x,
    const float* __restrict__ bl, const float* __restrict__ br)
{
    __shared__ float xs[32][DD];
    int base = blockIdx.x * 32;
    int tid = threadIdx.x;
    for (int i = tid; i < 32 * DD; i += 256) {
        int n = i >> 7, k = i & 127;
        int gn = base + n;
        xs[n][k] = (gn < NN) ? x[(size_t)gn * DD + k] : 0.f;
    }
    __syncthreads();

    int j = tid & 127;
    int sel = tid >> 7;
    const ull* Wp = (const ull*)(sel ? g_Wrp : g_Wlp);
    const float* bb = sel ? br : bl;
    float* gout = sel ? g_xr : g_xl;

    ull acc2[32];
#pragma unroll
    for (int n = 0; n < 32; n++) acc2[n] = 0ull;

#pragma unroll 2
    for (int k2 = 0; k2 < 64; k2 += 2) {
        ull w01 = Wp[k2 * 128 + j];
        ull w23 = Wp[(k2 + 1) * 128 + j];
#pragma unroll
        for (int n = 0; n < 32; n++) {
            ulonglong2 e = *(const ulonglong2*)&xs[n][k2 * 2];
            fma2(acc2[n], e.x, w01);
            fma2(acc2[n], e.y, w23);
        }
    }
    float bj = bb[j];
#pragma unroll
    for (int n = 0; n < 32; n++) {
        int gn = base + n;
        if (gn < NN) gout[(size_t)gn * DD + j] = sum2(acc2[n]) + bj;
    }
}

// ---------------- edge kernel: ee GEMV + logits + exp + atomic num/denom ----------------
__global__ void __launch_bounds__(128) k_edge(
    const float* __restrict__ ea,
    const int* __restrict__ ei,
    const float* __restrict__ att)
{
    __shared__ float es[32][DD];
    __shared__ int ssrc[32], sdst[32];
    int tid = threadIdx.x;
    int j = tid;
    float att_j = att[j];
    const ull* Wp = (const ull*)g_Wep;
    int ntiles = EE / 32;  // 25000, exact

    for (int t = blockIdx.x; t < ntiles; t += gridDim.x) {
        int ebase = t * 32;
        for (int i = tid; i < 32 * DD; i += 128) {
            int n = i >> 7, k = i & 127;
            es[n][k] = ea[(size_t)(ebase + n) * DD + k];
        }
        if (tid < 32) ssrc[tid] = ei[ebase + tid];
        else if (tid < 64) sdst[tid - 32] = ei[EE + ebase + (tid - 32)];
        __syncthreads();

        ull acc2[32];
#pragma unroll
        for (int n = 0; n < 32; n++) acc2[n] = 0ull;

#pragma unroll 2
        for (int k2 = 0; k2 < 64; k2 += 2) {
            ull w01 = Wp[k2 * 128 + j];
            ull w23 = Wp[(k2 + 1) * 128 + j];
#pragma unroll
            for (int n = 0; n < 32; n++) {
                ulonglong2 e = *(const ulonglong2*)&es[n][k2 * 2];
                fma2(acc2[n], e.x, w01);
                fma2(acc2[n], e.y, w23);
            }
        }

        // per-edge attention: logits, exp (no max-shift; mathematically identical),
        // atomic accumulation of numerator and denominator
#pragma unroll
        for (int n = 0; n < 32; n++) {
            int s = ssrc[n], d = sdst[n];
            float xls = g_xl[(size_t)s * DD + j];
            float xrd = g_xr[(size_t)d * DD + j];
            float mm = sum2(acc2[n]) + xls + xrd;
            mm = (mm > 0.f) ? mm : 0.2f * mm;   // leaky relu, slope 0.2
            float p = mm * att_j;
            p += __shfl_xor_sync(0xffffffffu, p, 8);
            p += __shfl_xor_sync(0xffffffffu, p, 4);
            p += __shfl_xor_sync(0xffffffffu, p, 2);
            p += __shfl_xor_sync(0xffffffffu, p, 1);
            float ex = __expf(p);               // per-head logit sum, all 16 lanes have it
            if ((tid & 15) == 0) atomicAdd(&g_denom[(size_t)d * HH + (j >> 4)], ex);
            atomicAdd(&g_num[(size_t)d * DD + j], ex * xls);
        }
        __syncthreads();
    }
}

// ---------------- attention finalize + residual + LN1 ----------------
__global__ void __launch_bounds__(128) k_attn_ln1(
    const float* __restrict__ x,
    const float* __restrict__ batt,
    const float* __restrict__ g1, const float* __restrict__ be1)
{
    int n = blockIdx.x, j = threadIdx.x;
    float num = g_num[(size_t)n * DD + j];
    float den = g_denom[n * HH + (j >> 4)];
    float y = x[(size_t)n * DD + j] + num / (den + 1e-16f) + batt[j];

    float s1 = y, s2 = y * y;
#pragma unroll
    for (int o = 16; o; o >>= 1) {
        s1 += __shfl_xor_sync(0xffffffffu, s1, o);
        s2 += __shfl_xor_sync(0xffffffffu, s2, o);
    }
    __shared__ float r1[4], r2[4];
    int w = j >> 5;
    if ((j & 31) == 0) { r1[w] = s1; r2[w] = s2; }
    __syncthreads();
    float t1 = r1[0] + r1[1] + r1[2] + r1[3];
    float t2 = r2[0] + r2[1] + r2[2] + r2[3];
    float mu = t1 * (1.f / 128.f);
    float var = t2 * (1.f / 128.f) - mu * mu;
    float rs = rsqrtf(var + 1e-5f);
    g_h1[(size_t)n * DD + j] = (y - mu) * rs * g1[j] + be1[j];
}

// ---------------- FFN (gelu exact) + residual + LN2 -> out ----------------
__global__ void __launch_bounds__(256) k_ffn(
    const float* __restrict__ b1,
    const float* __restrict__ b2,
    const float* __restrict__ g2, const float* __restrict__ be2,
    float* __restrict__ out)
{
    __shared__ float hs[16][DD];     // 8 KB
    __shared__ float hid[16][512];   // 32 KB
    int base = blockIdx.x * 16, tid = threadIdx.x;
    for (int i = tid; i < 16 * DD; i += 256) {
        int n = i >> 7, k = i & 127;
        int gn = base + n;
        hs[n][k] = (gn < NN) ? g_h1[(size_t)gn * DD + k] : 0.f;
    }
    __syncthreads();

    // phase A: hidden = gelu(h @ W1 + b1); each thread owns 2 hidden cols x 16 nodes
    const ull* W1p = (const ull*)g_W1p;
    ull a0[16], a1[16];
#pragma unroll
    for (int n = 0; n < 16; n++) { a0[n] = 0ull; a1[n] = 0ull; }
    int c0 = tid, c1 = tid + 256;
#pragma unroll 2
    for (int k2 = 0; k2 < 64; k2 += 2) {
        ull u01 = W1p[k2 * 512 + c0];
        ull u23 = W1p[(k2 + 1) * 512 + c0];
        ull v01 = W1p[k2 * 512 + c1];
        ull v23 = W1p[(k2 + 1) * 512 + c1];
#pragma unroll
        for (int n = 0; n < 16; n++) {
            ulonglong2 h = *(const ulonglong2*)&hs[n][k2 * 2];
            fma2(a0[n], h.x, u01);
            fma2(a0[n], h.y, u23);
            fma2(a1[n], h.x, v01);
            fma2(a1[n], h.y, v23);
        }
    }
    float bb0 = b1[c0], bb1 = b1[c1];
#pragma unroll
    for (int n = 0; n < 16; n++) {
        float v = sum2(a0[n]) + bb0;
        hid[n][c0] = 0.5f * v * (1.f + erff(v * 0.7071067811865475f));
        float u = sum2(a1[n]) + bb1;
        hid[n][c1] = 0.5f * u * (1.f + erff(u * 0.7071067811865475f));
    }
    __syncthreads();

    // phase B: o = hid @ W2; thread = (out col j, 8-node group)
    const ull* W2p = (const ull*)g_W2p;
    ull o2[8];
#pragma unroll
    for (int m = 0; m < 8; m++) o2[m] = 0ull;
    int j = tid & 127, ng = (tid >> 7) * 8;
#pragma unroll 2
    for (int k2 = 0; k2 < 256; k2 += 2) {
        ull w01 = W2p[k2 * 128 + j];
        ull w23 = W2p[(k2 + 1) * 128 + j];
#pragma unroll
        for (int m = 0; m < 8; m++) {
            ulonglong2 h = *(const ulonglong2*)&hid[ng + m][k2 * 2];
            fma2(o2[m], h.x, w01);
            fma2(o2[m], h.y, w23);
        }
    }
    float bj = b2[j];
    // residual back into hs (each (node,col) owned by exactly one thread)
#pragma unroll
    for (int m = 0; m < 8; m++) hs[ng + m][j] = sum2(o2[m]) + bj + hs[ng + m][j];
    __syncthreads();

    // LN2: 8 warps, 2 nodes each
    int w = tid >> 5, lane = tid & 31;
#pragma unroll
    for (int q = 0; q < 2; q++) {
        int nn2 = w * 2 + q;
        float v0 = hs[nn2][lane], v1 = hs[nn2][lane + 32];
        float v2 = hs[nn2][lane + 64], v3 = hs[nn2][lane + 96];
        float s1 = v0 + v1 + v2 + v3;
        float s2 = v0 * v0 + v1 * v1 + v2 * v2 + v3 * v3;
#pragma unroll
        for (int off = 16; off; off >>= 1) {
            s1 += __shfl_xor_sync(0xffffffffu, s1, off);
            s2 += __shfl_xor_sync(0xffffffffu, s2, off);
        }
        float mu = s1 * (1.f / 128.f);
        float var = s2 * (1.f / 128.f) - mu * mu;
        float rs = rsqrtf(var + 1e-5f);
        int gn = base + nn2;
        if (gn < NN) {
            size_t ob = (size_t)gn * DD;
            out[ob + lane]      = (v0 - mu) * rs * g2[lane]      + be2[lane];
            out[ob + lane + 32] = (v1 - mu) * rs * g2[lane + 32] + be2[lane + 32];
            out[ob + lane + 64] = (v2 - mu) * rs * g2[lane + 64] + be2[lane + 64];
            out[ob + lane + 96] = (v3 - mu) * rs * g2[lane + 96] + be2[lane + 96];
        }
    }
}

// ---------------- launch ----------------
extern "C" void kernel_launch(void* const* d_in, const int* in_sizes, int n_in,
                              void* d_out, int out_size)
{
    const float* x    = (const float*)d_in[0];
    const int*   ei   = (const int*)  d_in[1];
    const float* ea   = (const float*)d_in[2];
    // d_in[3] = batch (unused)
    const float* Wl   = (const float*)d_in[4];
    const float* bl   = (const float*)d_in[5];
    const float* Wr   = (const float*)d_in[6];
    const float* br   = (const float*)d_in[7];
    const float* We   = (const float*)d_in[8];
    const float* att  = (const float*)d_in[9];
    const float* batt = (const float*)d_in[10];
    const float* W1   = (const float*)d_in[11];
    const float* b1   = (const float*)d_in[12];
    const float* W2   = (const float*)d_in[13];
    const float* b2   = (const float*)d_in[14];
    const float* g1   = (const float*)d_in[15];
    const float* be1  = (const float*)d_in[16];
    const float* g2   = (const float*)d_in[17];
    const float* be2  = (const float*)d_in[18];
    float* out = (float*)d_out;

    int ztot = NN * DD + NN * HH;   // covers all init ranges (>= 64*512, 256*128)
    k_init<<<(ztot + 255) / 256, 256>>>(Wl, Wr, We, W1, W2);
    k_node_lin<<<(NN + 31) / 32, 256>>>(x, bl, br);
    k_edge<<<1184, 128>>>(ea, ei, att);
    k_attn_ln1<<<NN, 128>>>(x, batt, g1, be1);
    k_ffn<<<(NN + 15) / 16, 256>>>(b1, b2, g2, be2, out);
}